// round 4
// baseline (speedup 1.0000x reference)
#include <cuda_runtime.h>
#include <math.h>

#define NN 20000
#define EE 640000
#define HID 128

// ---------------- scratch (device globals; no allocation) ----------------
__device__ int   g_is64;
__device__ int   g_src[EE];
__device__ int   g_dst[EE];
__device__ int   g_csrc[EE];       // CSR: src ids grouped by dst
__device__ int   g_icnt[NN];       // in-degree (int)
__device__ int   g_rowptr[NN + 1];
__device__ int   g_cursor[NN];
__device__ int   g_part[64];       // block partial sums for scan
__device__ int   g_poff[64];       // exclusive offsets per scan block
__device__ float g_dinv[NN];       // rsqrt(deg+1)
__device__ float g_x  [NN * HID];
__device__ float g_h1 [NN * HID];
__device__ float g_ns [NN * HID];
__device__ float g_h2 [NN * HID];

// ---------------- small helpers ----------------
__device__ __forceinline__ float gelu_f(float x) {
    return 0.5f * x * (1.0f + erff(x * 0.70710678118654752440f));
}

// packed fp32x2 FMA (Blackwell): acc = a * b + acc, two lanes per instruction
__device__ __forceinline__ void fma2(unsigned long long& acc,
                                     unsigned long long a, unsigned long long b) {
    asm("fma.rn.f32x2 %0, %1, %2, %0;" : "+l"(acc) : "l"(a), "l"(b));
}
__device__ __forceinline__ unsigned long long dup2(float a) {
    unsigned long long r;
    asm("mov.b64 %0, {%1, %1};" : "=l"(r) : "f"(a));
    return r;
}
union F4U2 {
    float4 f;
    struct { unsigned long long lo, hi; } u;
    struct { float x, y, z, w; } s;
};

// ---------------- edge dtype detect (parallel) ----------------
__global__ void detect_dtype_k(const int* __restrict__ ei_words) {
    int hi = ei_words[2 * threadIdx.x + 1];          // 64 threads
    unsigned any = __ballot_sync(0xFFFFFFFFu, hi != 0);
    any |= __shfl_xor_sync(0xFFFFFFFFu, any, 0);     // noop, keep warp sync
    __shared__ unsigned s[2];
    s[threadIdx.x >> 5] = __ballot_sync(0xFFFFFFFFu, hi != 0);
    __syncthreads();
    if (threadIdx.x == 0) g_is64 = ((s[0] | s[1]) == 0u) ? 1 : 0;
}

__global__ void zero_cnt_k(int n) {
    int i = blockIdx.x * blockDim.x + threadIdx.x;
    if (i < n) g_icnt[i] = 0;
}

// convert + count in one pass over edges
__global__ void convert_count_k(const void* __restrict__ ei, int E) {
    int e = blockIdx.x * blockDim.x + threadIdx.x;
    if (e >= E) return;
    int s, d;
    if (g_is64) {
        const long long* p = (const long long*)ei;
        s = (int)p[e];
        d = (int)p[E + e];
    } else {
        const int* p = (const int*)ei;
        s = p[e];
        d = p[E + e];
    }
    g_src[e] = s;
    g_dst[e] = d;
    atomicAdd(&g_icnt[d], 1);
}

// ---------------- parallel exclusive scan over degrees (3 phases) ----------------
// Phase A: per-block (1024 elems) partial sums
__global__ void __launch_bounds__(1024) scanA_k(int n) {
    __shared__ int wsum[32];
    int i = blockIdx.x * 1024 + threadIdx.x;
    int v = (i < n) ? g_icnt[i] : 0;
    int s = v;
    #pragma unroll
    for (int off = 16; off > 0; off >>= 1) s += __shfl_xor_sync(0xFFFFFFFFu, s, off);
    if ((threadIdx.x & 31) == 0) wsum[threadIdx.x >> 5] = s;
    __syncthreads();
    if (threadIdx.x < 32) {
        int t = wsum[threadIdx.x];
        #pragma unroll
        for (int off = 16; off > 0; off >>= 1) t += __shfl_xor_sync(0xFFFFFFFFu, t, off);
        if (threadIdx.x == 0) g_part[blockIdx.x] = t;
    }
}

// Phase B: 1 warp scans the <=64 block partials -> exclusive offsets, rowptr[n]=total
__global__ void scanB_k(int nblocks, int n) {
    int t = threadIdx.x;                       // 64 threads
    int v = (t < nblocks) ? g_part[t] : 0;
    int incl = v;
    // inclusive scan over 64 via shfl within warp + cross-warp fix
    #pragma unroll
    for (int off = 1; off < 32; off <<= 1) {
        int u = __shfl_up_sync(0xFFFFFFFFu, incl, off);
        if ((t & 31) >= off) incl += u;
    }
    __shared__ int w0sum;
    if (t == 31) w0sum = incl;
    __syncthreads();
    if (t >= 32) incl += w0sum;
    g_poff[t] = incl - v;                      // exclusive
    if (t == 63) g_rowptr[n] = incl;           // grand total (= E)
}

// Phase C: per-block exclusive scan + offset; write rowptr/cursor/dinv
__global__ void __launch_bounds__(1024) scanC_k(int n) {
    __shared__ int wsum[32];
    int tid = threadIdx.x;
    int i = blockIdx.x * 1024 + tid;
    int c = (i < n) ? g_icnt[i] : 0;
    int lane = tid & 31, wid = tid >> 5;
    int incl = c;
    #pragma unroll
    for (int off = 1; off < 32; off <<= 1) {
        int u = __shfl_up_sync(0xFFFFFFFFu, incl, off);
        if (lane >= off) incl += u;
    }
    if (lane == 31) wsum[wid] = incl;
    __syncthreads();
    if (wid == 0) {
        int t = (lane < 32) ? wsum[lane] : 0;
        #pragma unroll
        for (int off = 1; off < 32; off <<= 1) {
            int u = __shfl_up_sync(0xFFFFFFFFu, t, off);
            if (lane >= off) t += u;
        }
        wsum[lane] = t;
    }
    __syncthreads();
    int warp_off = (wid == 0) ? 0 : wsum[wid - 1];
    int run = g_poff[blockIdx.x] + warp_off + incl - c;   // exclusive
    if (i < n) {
        g_rowptr[i] = run;
        g_cursor[i] = run;
        g_dinv[i]   = rsqrtf((float)c + 1.0f);
    }
}

__global__ void fill_k(int E) {
    int e = blockIdx.x * blockDim.x + threadIdx.x;
    if (e >= E) return;
    int d = g_dst[e];
    int slot = atomicAdd(&g_cursor[d], 1);
    g_csrc[slot] = g_src[e];
}

// ---------------- GCN gather: h1 = relu(sum_neigh x[s]*dinv[s]dinv[d] + x[d]*dinv[d]^2 + b)
__global__ void gcn_gather_k(const float* __restrict__ bias, int n) {
    int node = blockIdx.x * (blockDim.x >> 5) + (threadIdx.x >> 5);
    if (node >= n) return;
    int lane = threadIdx.x & 31;
    int beg = g_rowptr[node], end = g_rowptr[node + 1];
    float dd = g_dinv[node];
    const float* xd = g_x + (size_t)node * HID;
    float sl = dd * dd;
    float a0 = xd[lane] * sl;
    float a1 = xd[lane + 32] * sl;
    float a2 = xd[lane + 64] * sl;
    float a3 = xd[lane + 96] * sl;

    int e = beg;
    for (; e + 1 < end; e += 2) {
        int s0 = g_csrc[e], s1 = g_csrc[e + 1];
        float c0 = g_dinv[s0] * dd, c1 = g_dinv[s1] * dd;
        const float* x0 = g_x + (size_t)s0 * HID;
        const float* x1 = g_x + (size_t)s1 * HID;
        float v00 = x0[lane],      v01 = x1[lane];
        float v10 = x0[lane + 32], v11 = x1[lane + 32];
        float v20 = x0[lane + 64], v21 = x1[lane + 64];
        float v30 = x0[lane + 96], v31 = x1[lane + 96];
        a0 = fmaf(v00, c0, a0); a0 = fmaf(v01, c1, a0);
        a1 = fmaf(v10, c0, a1); a1 = fmaf(v11, c1, a1);
        a2 = fmaf(v20, c0, a2); a2 = fmaf(v21, c1, a2);
        a3 = fmaf(v30, c0, a3); a3 = fmaf(v31, c1, a3);
    }
    if (e < end) {
        int s0 = g_csrc[e];
        float c0 = g_dinv[s0] * dd;
        const float* x0 = g_x + (size_t)s0 * HID;
        a0 = fmaf(x0[lane],      c0, a0);
        a1 = fmaf(x0[lane + 32], c0, a1);
        a2 = fmaf(x0[lane + 64], c0, a2);
        a3 = fmaf(x0[lane + 96], c0, a3);
    }
    float* out = g_h1 + (size_t)node * HID;
    out[lane]      = fmaxf(a0 + bias[lane],      0.0f);
    out[lane + 32] = fmaxf(a1 + bias[lane + 32], 0.0f);
    out[lane + 64] = fmaxf(a2 + bias[lane + 64], 0.0f);
    out[lane + 96] = fmaxf(a3 + bias[lane + 96], 0.0f);
}

// ---------------- SAGE gather: ns = mean_neigh h1[s]
__global__ void sage_gather_k(int n) {
    int node = blockIdx.x * (blockDim.x >> 5) + (threadIdx.x >> 5);
    if (node >= n) return;
    int lane = threadIdx.x & 31;
    int beg = g_rowptr[node], end = g_rowptr[node + 1];
    float a0 = 0.f, a1 = 0.f, a2 = 0.f, a3 = 0.f;
    int e = beg;
    for (; e + 1 < end; e += 2) {
        int s0 = g_csrc[e], s1 = g_csrc[e + 1];
        const float* x0 = g_h1 + (size_t)s0 * HID;
        const float* x1 = g_h1 + (size_t)s1 * HID;
        a0 += x0[lane];      a0 += x1[lane];
        a1 += x0[lane + 32]; a1 += x1[lane + 32];
        a2 += x0[lane + 64]; a2 += x1[lane + 64];
        a3 += x0[lane + 96]; a3 += x1[lane + 96];
    }
    if (e < end) {
        int s0 = g_csrc[e];
        const float* x0 = g_h1 + (size_t)s0 * HID;
        a0 += x0[lane]; a1 += x0[lane + 32]; a2 += x0[lane + 64]; a3 += x0[lane + 96];
    }
    int deg = end - beg;
    float inv = 1.0f / (float)max(deg, 1);
    float* out = g_ns + (size_t)node * HID;
    out[lane]      = a0 * inv;
    out[lane + 32] = a1 * inv;
    out[lane + 64] = a2 * inv;
    out[lane + 96] = a3 * inv;
}

// ---------------- GEMM via packed f32x2, TN=8: C[n,BN] = act(A@W + bias) ----------------
// Per k4 per thread: 12 LDG.128, 16 dup-movs, 64 fma2  -> FMA2-issue bound.
template<int BN, int ACT>
__global__ void __launch_bounds__(256) gemm_k(
    const float* __restrict__ A, const float* __restrict__ W,
    const float* __restrict__ bias,
    float* __restrict__ C, int nrows)
{
    constexpr int TN  = 8;
    constexpr int CT  = BN / TN;       // 16 (BN=128) or 8 (BN=64)
    constexpr int RT  = 256 / CT;      // 16 or 32
    constexpr int RPT = 4;
    constexpr int BM  = RT * RPT;      // 64 or 128
    const int tid  = threadIdx.x;
    const int tc   = tid % CT;
    const int tr   = tid / CT;
    const int row0 = blockIdx.x * BM + tr * RPT;
    const int col0 = tc * TN;
    if (row0 >= nrows) return;

    unsigned long long acc[RPT][4];
    #pragma unroll
    for (int r = 0; r < RPT; r++)
        #pragma unroll
        for (int j = 0; j < 4; j++) acc[r][j] = 0ull;

    for (int k4 = 0; k4 < 128; k4 += 4) {
        F4U2 wa[4], wb[4];
        #pragma unroll
        for (int kk = 0; kk < 4; kk++) {
            wa[kk].f = *(const float4*)&W[(k4 + kk) * BN + col0];
            wb[kk].f = *(const float4*)&W[(k4 + kk) * BN + col0 + 4];
        }
        #pragma unroll
        for (int r = 0; r < RPT; r++) {
            F4U2 a;
            a.f = *(const float4*)&A[(size_t)(row0 + r) * 128 + k4];
            unsigned long long d0 = dup2(a.s.x), d1 = dup2(a.s.y),
                               d2 = dup2(a.s.z), d3 = dup2(a.s.w);
            fma2(acc[r][0], d0, wa[0].u.lo); fma2(acc[r][1], d0, wa[0].u.hi);
            fma2(acc[r][2], d0, wb[0].u.lo); fma2(acc[r][3], d0, wb[0].u.hi);
            fma2(acc[r][0], d1, wa[1].u.lo); fma2(acc[r][1], d1, wa[1].u.hi);
            fma2(acc[r][2], d1, wb[1].u.lo); fma2(acc[r][3], d1, wb[1].u.hi);
            fma2(acc[r][0], d2, wa[2].u.lo); fma2(acc[r][1], d2, wa[2].u.hi);
            fma2(acc[r][2], d2, wb[2].u.lo); fma2(acc[r][3], d2, wb[2].u.hi);
            fma2(acc[r][0], d3, wa[3].u.lo); fma2(acc[r][1], d3, wa[3].u.hi);
            fma2(acc[r][2], d3, wb[3].u.lo); fma2(acc[r][3], d3, wb[3].u.hi);
        }
    }

    #pragma unroll
    for (int r = 0; r < RPT; r++) {
        F4U2 oa, ob;
        oa.u.lo = acc[r][0]; oa.u.hi = acc[r][1];
        ob.u.lo = acc[r][2]; ob.u.hi = acc[r][3];
        float v[8] = {oa.s.x, oa.s.y, oa.s.z, oa.s.w, ob.s.x, ob.s.y, ob.s.z, ob.s.w};
        #pragma unroll
        for (int c = 0; c < 8; c++) {
            float t = v[c];
            if (bias) t += bias[col0 + c];
            if (ACT == 1) t = fmaxf(t, 0.0f);
            if (ACT == 2) t = gelu_f(t);
            v[c] = t;
        }
        oa.s.x = v[0]; oa.s.y = v[1]; oa.s.z = v[2]; oa.s.w = v[3];
        ob.s.x = v[4]; ob.s.y = v[5]; ob.s.z = v[6]; ob.s.w = v[7];
        *(float4*)&C[(size_t)(row0 + r) * BN + col0]     = oa.f;
        *(float4*)&C[(size_t)(row0 + r) * BN + col0 + 4] = ob.f;
    }
}

// fused SAGE GEMM: h2 = relu(ns@Wl + h1@Wr + bl)
__global__ void __launch_bounds__(256) gemm2_k(
    const float* __restrict__ A1, const float* __restrict__ W1,
    const float* __restrict__ A2, const float* __restrict__ W2,
    const float* __restrict__ bias,
    float* __restrict__ C, int nrows)
{
    constexpr int BN = 128, TN = 8, CT = 16, RPT = 4, BM = 64;
    const int tid  = threadIdx.x;
    const int tc   = tid % CT;
    const int tr   = tid / CT;
    const int row0 = blockIdx.x * BM + tr * RPT;
    const int col0 = tc * TN;
    if (row0 >= nrows) return;

    unsigned long long acc[RPT][4];
    #pragma unroll
    for (int r = 0; r < RPT; r++)
        #pragma unroll
        for (int j = 0; j < 4; j++) acc[r][j] = 0ull;

    #pragma unroll 1
    for (int pass = 0; pass < 2; pass++) {
        const float* A = pass ? A2 : A1;
        const float* W = pass ? W2 : W1;
        for (int k4 = 0; k4 < 128; k4 += 4) {
            F4U2 wa[4], wb[4];
            #pragma unroll
            for (int kk = 0; kk < 4; kk++) {
                wa[kk].f = *(const float4*)&W[(k4 + kk) * BN + col0];
                wb[kk].f = *(const float4*)&W[(k4 + kk) * BN + col0 + 4];
            }
            #pragma unroll
            for (int r = 0; r < RPT; r++) {
                F4U2 a;
                a.f = *(const float4*)&A[(size_t)(row0 + r) * 128 + k4];
                unsigned long long d0 = dup2(a.s.x), d1 = dup2(a.s.y),
                                   d2 = dup2(a.s.z), d3 = dup2(a.s.w);
                fma2(acc[r][0], d0, wa[0].u.lo); fma2(acc[r][1], d0, wa[0].u.hi);
                fma2(acc[r][2], d0, wb[0].u.lo); fma2(acc[r][3], d0, wb[0].u.hi);
                fma2(acc[r][0], d1, wa[1].u.lo); fma2(acc[r][1], d1, wa[1].u.hi);
                fma2(acc[r][2], d1, wb[1].u.lo); fma2(acc[r][3], d1, wb[1].u.hi);
                fma2(acc[r][0], d2, wa[2].u.lo); fma2(acc[r][1], d2, wa[2].u.hi);
                fma2(acc[r][2], d2, wb[2].u.lo); fma2(acc[r][3], d2, wb[2].u.hi);
                fma2(acc[r][0], d3, wa[3].u.lo); fma2(acc[r][1], d3, wa[3].u.hi);
                fma2(acc[r][2], d3, wb[3].u.lo); fma2(acc[r][3], d3, wb[3].u.hi);
            }
        }
    }

    #pragma unroll
    for (int r = 0; r < RPT; r++) {
        F4U2 oa, ob;
        oa.u.lo = acc[r][0]; oa.u.hi = acc[r][1];
        ob.u.lo = acc[r][2]; ob.u.hi = acc[r][3];
        oa.s.x = fmaxf(oa.s.x + bias[col0 + 0], 0.0f);
        oa.s.y = fmaxf(oa.s.y + bias[col0 + 1], 0.0f);
        oa.s.z = fmaxf(oa.s.z + bias[col0 + 2], 0.0f);
        oa.s.w = fmaxf(oa.s.w + bias[col0 + 3], 0.0f);
        ob.s.x = fmaxf(ob.s.x + bias[col0 + 4], 0.0f);
        ob.s.y = fmaxf(ob.s.y + bias[col0 + 5], 0.0f);
        ob.s.z = fmaxf(ob.s.z + bias[col0 + 6], 0.0f);
        ob.s.w = fmaxf(ob.s.w + bias[col0 + 7], 0.0f);
        *(float4*)&C[(size_t)(row0 + r) * BN + col0]     = oa.f;
        *(float4*)&C[(size_t)(row0 + r) * BN + col0 + 4] = ob.f;
    }
}

// ---------------- value head: out[i] = dot(h2[i], Wv) + bv ----------------
__global__ void value_k(const float* __restrict__ Wv, const float* __restrict__ bv,
                        float* __restrict__ out, int n)
{
    int i = blockIdx.x * (blockDim.x >> 5) + (threadIdx.x >> 5);
    int lane = threadIdx.x & 31;
    if (i >= n) return;
    const float* h = g_h2 + (size_t)i * HID;
    float s = 0.0f;
    #pragma unroll
    for (int q = 0; q < 4; q++) {
        int j = lane + 32 * q;
        s = fmaf(h[j], Wv[j], s);
    }
    #pragma unroll
    for (int off = 16; off > 0; off >>= 1)
        s += __shfl_xor_sync(0xFFFFFFFFu, s, off);
    if (lane == 0) out[i] = s + bv[0];
}

// ---------------- launch ----------------
extern "C" void kernel_launch(void* const* d_in, const int* in_sizes, int n_in,
                              void* d_out, int out_size)
{
    const float* feat     = (const float*)d_in[0];
    const void*  ei       = d_in[1];
    const float* W_gcn    = (const float*)d_in[2];
    const float* b_gcn    = (const float*)d_in[3];
    const float* W_sage_l = (const float*)d_in[4];
    const float* b_sage_l = (const float*)d_in[5];
    const float* W_sage_r = (const float*)d_in[6];
    const float* W1       = (const float*)d_in[7];
    const float* b1       = (const float*)d_in[8];
    const float* W2       = (const float*)d_in[9];
    const float* b2       = (const float*)d_in[10];
    const float* W3       = (const float*)d_in[11];
    const float* b3       = (const float*)d_in[12];
    const float* Wv       = (const float*)d_in[13];
    const float* bv       = (const float*)d_in[14];

    const int N = in_sizes[0] / HID;   // 20000
    const int E = in_sizes[1] / 2;     // 640000

    float* means_out  = (float*)d_out;            // [N, 64]
    float* values_out = (float*)d_out + (size_t)N * 64;

    float *p_x, *p_h1, *p_ns, *p_h2;
    cudaGetSymbolAddress((void**)&p_x,  g_x);
    cudaGetSymbolAddress((void**)&p_h1, g_h1);
    cudaGetSymbolAddress((void**)&p_ns, g_ns);
    cudaGetSymbolAddress((void**)&p_h2, g_h2);

    const int TB = 256;
    const int e_blocks  = (E + TB - 1) / TB;
    const int nw_blocks = (N * 32 + TB - 1) / TB;   // warp per node
    const int scan_blocks = (N + 1023) / 1024;      // 20

    // 1) CSR build
    detect_dtype_k<<<1, 64>>>((const int*)ei);
    zero_cnt_k<<<(N + TB - 1) / TB, TB>>>(N);
    convert_count_k<<<e_blocks, TB>>>(ei, E);
    scanA_k<<<scan_blocks, 1024>>>(N);
    scanB_k<<<1, 64>>>(scan_blocks, N);
    scanC_k<<<scan_blocks, 1024>>>(N);
    fill_k<<<e_blocks, TB>>>(E);

    // 2) GCN: x = feat @ W_gcn ; gather(+selfloop+bias+relu)
    gemm_k<128, 0><<<(N + 63) / 64, TB>>>(feat, W_gcn, nullptr, p_x, N);
    gcn_gather_k<<<nw_blocks, TB>>>(b_gcn, N);

    // 3) SAGE: neighbor mean ; h2 = relu(mean@Wl + h@Wr + bl)  (fused)
    sage_gather_k<<<nw_blocks, TB>>>(N);
    gemm2_k<<<(N + 63) / 64, TB>>>(p_ns, W_sage_l, p_h1, W_sage_r, b_sage_l, p_h2, N);

    // 4) policy MLP
    gemm_k<128, 2><<<(N + 63) / 64, TB>>>(p_h2, W1, b1, p_x, N);
    gemm_k<128, 2><<<(N + 63) / 64, TB>>>(p_x, W2, b2, p_ns, N);
    gemm_k<64, 0><<<(N + 127) / 128, TB>>>(p_ns, W3, b3, means_out, N);

    // 5) value head
    value_k<<<(N + 7) / 8, TB>>>(Wv, bv, values_out, N);
}

// round 5
// speedup vs baseline: 1.2895x; 1.2895x over previous
#include <cuda_runtime.h>
#include <math.h>

#define NN 20000
#define EE 640000
#define HID 128

// ---------------- scratch (device globals; no allocation) ----------------
__device__ int   g_is64;
__device__ int   g_src[EE];
__device__ int   g_dst[EE];
__device__ int   g_csrc[EE];       // CSR: src ids grouped by dst
__device__ int   g_icnt[NN];       // in-degree (int)
__device__ int   g_rowptr[NN + 1];
__device__ int   g_cursor[NN];
__device__ int   g_part[64];       // block partial sums for scan
__device__ int   g_poff[64];       // exclusive offsets per scan block
__device__ float g_dinv[NN];       // rsqrt(deg+1)
__device__ float g_x  [NN * HID];
__device__ float g_h1 [NN * HID];
__device__ float g_ns [NN * HID];
__device__ float g_h2 [NN * HID];

// ---------------- small helpers ----------------
__device__ __forceinline__ float gelu_f(float x) {
    return 0.5f * x * (1.0f + erff(x * 0.70710678118654752440f));
}

// packed fp32x2 FMA (Blackwell): acc = a * b + acc, two lanes per instruction
__device__ __forceinline__ void fma2(unsigned long long& acc,
                                     unsigned long long a, unsigned long long b) {
    asm("fma.rn.f32x2 %0, %1, %2, %0;" : "+l"(acc) : "l"(a), "l"(b));
}
__device__ __forceinline__ unsigned long long dup2(float a) {
    unsigned long long r;
    asm("mov.b64 %0, {%1, %1};" : "=l"(r) : "f"(a));
    return r;
}
union F4U2 {
    float4 f;
    struct { unsigned long long lo, hi; } u;
    struct { float x, y, z, w; } s;
};

// ---------------- edge dtype detect (parallel) ----------------
__global__ void detect_dtype_k(const int* __restrict__ ei_words) {
    int hi = ei_words[2 * threadIdx.x + 1];          // 64 threads
    __shared__ unsigned s[2];
    s[threadIdx.x >> 5] = __ballot_sync(0xFFFFFFFFu, hi != 0);
    __syncthreads();
    if (threadIdx.x == 0) g_is64 = ((s[0] | s[1]) == 0u) ? 1 : 0;
}

__global__ void zero_cnt_k(int n) {
    int i = blockIdx.x * blockDim.x + threadIdx.x;
    if (i < n) g_icnt[i] = 0;
}

// convert + count in one pass over edges
__global__ void convert_count_k(const void* __restrict__ ei, int E) {
    int e = blockIdx.x * blockDim.x + threadIdx.x;
    if (e >= E) return;
    int s, d;
    if (g_is64) {
        const long long* p = (const long long*)ei;
        s = (int)p[e];
        d = (int)p[E + e];
    } else {
        const int* p = (const int*)ei;
        s = p[e];
        d = p[E + e];
    }
    g_src[e] = s;
    g_dst[e] = d;
    atomicAdd(&g_icnt[d], 1);
}

// ---------------- parallel exclusive scan over degrees (3 phases) ----------------
__global__ void __launch_bounds__(1024) scanA_k(int n) {
    __shared__ int wsum[32];
    int i = blockIdx.x * 1024 + threadIdx.x;
    int v = (i < n) ? g_icnt[i] : 0;
    int s = v;
    #pragma unroll
    for (int off = 16; off > 0; off >>= 1) s += __shfl_xor_sync(0xFFFFFFFFu, s, off);
    if ((threadIdx.x & 31) == 0) wsum[threadIdx.x >> 5] = s;
    __syncthreads();
    if (threadIdx.x < 32) {
        int t = wsum[threadIdx.x];
        #pragma unroll
        for (int off = 16; off > 0; off >>= 1) t += __shfl_xor_sync(0xFFFFFFFFu, t, off);
        if (threadIdx.x == 0) g_part[blockIdx.x] = t;
    }
}

__global__ void scanB_k(int nblocks, int n) {
    int t = threadIdx.x;                       // 64 threads
    int v = (t < nblocks) ? g_part[t] : 0;
    int incl = v;
    #pragma unroll
    for (int off = 1; off < 32; off <<= 1) {
        int u = __shfl_up_sync(0xFFFFFFFFu, incl, off);
        if ((t & 31) >= off) incl += u;
    }
    __shared__ int w0sum;
    if (t == 31) w0sum = incl;
    __syncthreads();
    if (t >= 32) incl += w0sum;
    g_poff[t] = incl - v;                      // exclusive
    if (t == 63) g_rowptr[n] = incl;           // grand total (= E)
}

__global__ void __launch_bounds__(1024) scanC_k(int n) {
    __shared__ int wsum[32];
    int tid = threadIdx.x;
    int i = blockIdx.x * 1024 + tid;
    int c = (i < n) ? g_icnt[i] : 0;
    int lane = tid & 31, wid = tid >> 5;
    int incl = c;
    #pragma unroll
    for (int off = 1; off < 32; off <<= 1) {
        int u = __shfl_up_sync(0xFFFFFFFFu, incl, off);
        if (lane >= off) incl += u;
    }
    if (lane == 31) wsum[wid] = incl;
    __syncthreads();
    if (wid == 0) {
        int t = wsum[lane];
        #pragma unroll
        for (int off = 1; off < 32; off <<= 1) {
            int u = __shfl_up_sync(0xFFFFFFFFu, t, off);
            if (lane >= off) t += u;
        }
        wsum[lane] = t;
    }
    __syncthreads();
    int warp_off = (wid == 0) ? 0 : wsum[wid - 1];
    int run = g_poff[blockIdx.x] + warp_off + incl - c;   // exclusive
    if (i < n) {
        g_rowptr[i] = run;
        g_cursor[i] = run;
        g_dinv[i]   = rsqrtf((float)c + 1.0f);
    }
}

__global__ void fill_k(int E) {
    int e = blockIdx.x * blockDim.x + threadIdx.x;
    if (e >= E) return;
    int d = g_dst[e];
    int slot = atomicAdd(&g_cursor[d], 1);
    g_csrc[slot] = g_src[e];
}

// ---------------- GCN gather: h1 = relu(sum_neigh x[s]*dinv[s]dinv[d] + x[d]*dinv[d]^2 + b)
__global__ void gcn_gather_k(const float* __restrict__ bias, int n) {
    int node = blockIdx.x * (blockDim.x >> 5) + (threadIdx.x >> 5);
    if (node >= n) return;
    int lane = threadIdx.x & 31;
    int beg = g_rowptr[node], end = g_rowptr[node + 1];
    float dd = g_dinv[node];
    const float* xd = g_x + (size_t)node * HID;
    float sl = dd * dd;
    float a0 = xd[lane] * sl;
    float a1 = xd[lane + 32] * sl;
    float a2 = xd[lane + 64] * sl;
    float a3 = xd[lane + 96] * sl;

    int e = beg;
    for (; e + 1 < end; e += 2) {
        int s0 = g_csrc[e], s1 = g_csrc[e + 1];
        float c0 = g_dinv[s0] * dd, c1 = g_dinv[s1] * dd;
        const float* x0 = g_x + (size_t)s0 * HID;
        const float* x1 = g_x + (size_t)s1 * HID;
        float v00 = x0[lane],      v01 = x1[lane];
        float v10 = x0[lane + 32], v11 = x1[lane + 32];
        float v20 = x0[lane + 64], v21 = x1[lane + 64];
        float v30 = x0[lane + 96], v31 = x1[lane + 96];
        a0 = fmaf(v00, c0, a0); a0 = fmaf(v01, c1, a0);
        a1 = fmaf(v10, c0, a1); a1 = fmaf(v11, c1, a1);
        a2 = fmaf(v20, c0, a2); a2 = fmaf(v21, c1, a2);
        a3 = fmaf(v30, c0, a3); a3 = fmaf(v31, c1, a3);
    }
    if (e < end) {
        int s0 = g_csrc[e];
        float c0 = g_dinv[s0] * dd;
        const float* x0 = g_x + (size_t)s0 * HID;
        a0 = fmaf(x0[lane],      c0, a0);
        a1 = fmaf(x0[lane + 32], c0, a1);
        a2 = fmaf(x0[lane + 64], c0, a2);
        a3 = fmaf(x0[lane + 96], c0, a3);
    }
    float* out = g_h1 + (size_t)node * HID;
    out[lane]      = fmaxf(a0 + bias[lane],      0.0f);
    out[lane + 32] = fmaxf(a1 + bias[lane + 32], 0.0f);
    out[lane + 64] = fmaxf(a2 + bias[lane + 64], 0.0f);
    out[lane + 96] = fmaxf(a3 + bias[lane + 96], 0.0f);
}

// ---------------- SAGE gather: ns = mean_neigh h1[s]
__global__ void sage_gather_k(int n) {
    int node = blockIdx.x * (blockDim.x >> 5) + (threadIdx.x >> 5);
    if (node >= n) return;
    int lane = threadIdx.x & 31;
    int beg = g_rowptr[node], end = g_rowptr[node + 1];
    float a0 = 0.f, a1 = 0.f, a2 = 0.f, a3 = 0.f;
    int e = beg;
    for (; e + 1 < end; e += 2) {
        int s0 = g_csrc[e], s1 = g_csrc[e + 1];
        const float* x0 = g_h1 + (size_t)s0 * HID;
        const float* x1 = g_h1 + (size_t)s1 * HID;
        a0 += x0[lane];      a0 += x1[lane];
        a1 += x0[lane + 32]; a1 += x1[lane + 32];
        a2 += x0[lane + 64]; a2 += x1[lane + 64];
        a3 += x0[lane + 96]; a3 += x1[lane + 96];
    }
    if (e < end) {
        int s0 = g_csrc[e];
        const float* x0 = g_h1 + (size_t)s0 * HID;
        a0 += x0[lane]; a1 += x0[lane + 32]; a2 += x0[lane + 64]; a3 += x0[lane + 96];
    }
    int deg = end - beg;
    float inv = 1.0f / (float)max(deg, 1);
    float* out = g_ns + (size_t)node * HID;
    out[lane]      = a0 * inv;
    out[lane + 32] = a1 * inv;
    out[lane + 64] = a2 * inv;
    out[lane + 96] = a3 * inv;
}

// ---------------- GEMM via packed f32x2 (TN=4, CT=32: warp-uniform A loads) ----------------
template<int BN, int ACT>
__global__ void __launch_bounds__(256) gemm_k(
    const float* __restrict__ A, const float* __restrict__ W,
    const float* __restrict__ bias,
    float* __restrict__ C, int nrows)
{
    constexpr int TN  = 4;
    constexpr int CT  = BN / TN;       // col-threads (32 or 16)
    constexpr int RT  = 256 / CT;      // row-groups
    constexpr int BM  = 32;
    constexpr int RPT = BM / RT;
    const int tid  = threadIdx.x;
    const int tc   = tid % CT;
    const int tr   = tid / CT;
    const int row0 = blockIdx.x * BM + tr * RPT;
    const int col0 = tc * TN;
    if (row0 >= nrows) return;

    unsigned long long acc[RPT][2];
    #pragma unroll
    for (int r = 0; r < RPT; r++) { acc[r][0] = 0ull; acc[r][1] = 0ull; }

    for (int k4 = 0; k4 < 128; k4 += 4) {
        F4U2 w0, w1, w2, w3;
        w0.f = *(const float4*)&W[(k4 + 0) * BN + col0];
        w1.f = *(const float4*)&W[(k4 + 1) * BN + col0];
        w2.f = *(const float4*)&W[(k4 + 2) * BN + col0];
        w3.f = *(const float4*)&W[(k4 + 3) * BN + col0];
        #pragma unroll
        for (int r = 0; r < RPT; r++) {
            F4U2 a;
            a.f = *(const float4*)&A[(size_t)(row0 + r) * 128 + k4];
            unsigned long long ax = dup2(a.s.x), ay = dup2(a.s.y),
                               az = dup2(a.s.z), aw = dup2(a.s.w);
            fma2(acc[r][0], ax, w0.u.lo); fma2(acc[r][1], ax, w0.u.hi);
            fma2(acc[r][0], ay, w1.u.lo); fma2(acc[r][1], ay, w1.u.hi);
            fma2(acc[r][0], az, w2.u.lo); fma2(acc[r][1], az, w2.u.hi);
            fma2(acc[r][0], aw, w3.u.lo); fma2(acc[r][1], aw, w3.u.hi);
        }
    }

    #pragma unroll
    for (int r = 0; r < RPT; r++) {
        F4U2 o;
        o.u.lo = acc[r][0]; o.u.hi = acc[r][1];
        float v[4] = {o.s.x, o.s.y, o.s.z, o.s.w};
        #pragma unroll
        for (int c = 0; c < TN; c++) {
            float t = v[c];
            if (bias) t += bias[col0 + c];
            if (ACT == 1) t = fmaxf(t, 0.0f);
            if (ACT == 2) t = gelu_f(t);
            v[c] = t;
        }
        o.s.x = v[0]; o.s.y = v[1]; o.s.z = v[2]; o.s.w = v[3];
        *(float4*)&C[(size_t)(row0 + r) * BN + col0] = o.f;
    }
}

// fused SAGE GEMM: h2 = relu(ns@Wl + h1@Wr + bl)
__global__ void __launch_bounds__(256) gemm2_k(
    const float* __restrict__ A1, const float* __restrict__ W1,
    const float* __restrict__ A2, const float* __restrict__ W2,
    const float* __restrict__ bias,
    float* __restrict__ C, int nrows)
{
    constexpr int BN = 128, TN = 4, CT = 32, RT = 8, BM = 32, RPT = 4;
    const int tid  = threadIdx.x;
    const int tc   = tid % CT;
    const int tr   = tid / CT;
    const int row0 = blockIdx.x * BM + tr * RPT;
    const int col0 = tc * TN;
    if (row0 >= nrows) return;

    unsigned long long acc[RPT][2];
    #pragma unroll
    for (int r = 0; r < RPT; r++) { acc[r][0] = 0ull; acc[r][1] = 0ull; }

    #pragma unroll 1
    for (int pass = 0; pass < 2; pass++) {
        const float* A = pass ? A2 : A1;
        const float* W = pass ? W2 : W1;
        for (int k4 = 0; k4 < 128; k4 += 4) {
            F4U2 w0, w1, w2, w3;
            w0.f = *(const float4*)&W[(k4 + 0) * BN + col0];
            w1.f = *(const float4*)&W[(k4 + 1) * BN + col0];
            w2.f = *(const float4*)&W[(k4 + 2) * BN + col0];
            w3.f = *(const float4*)&W[(k4 + 3) * BN + col0];
            #pragma unroll
            for (int r = 0; r < RPT; r++) {
                F4U2 a;
                a.f = *(const float4*)&A[(size_t)(row0 + r) * 128 + k4];
                unsigned long long ax = dup2(a.s.x), ay = dup2(a.s.y),
                                   az = dup2(a.s.z), aw = dup2(a.s.w);
                fma2(acc[r][0], ax, w0.u.lo); fma2(acc[r][1], ax, w0.u.hi);
                fma2(acc[r][0], ay, w1.u.lo); fma2(acc[r][1], ay, w1.u.hi);
                fma2(acc[r][0], az, w2.u.lo); fma2(acc[r][1], az, w2.u.hi);
                fma2(acc[r][0], aw, w3.u.lo); fma2(acc[r][1], aw, w3.u.hi);
            }
        }
    }

    #pragma unroll
    for (int r = 0; r < RPT; r++) {
        F4U2 o;
        o.u.lo = acc[r][0]; o.u.hi = acc[r][1];
        o.s.x = fmaxf(o.s.x + bias[col0 + 0], 0.0f);
        o.s.y = fmaxf(o.s.y + bias[col0 + 1], 0.0f);
        o.s.z = fmaxf(o.s.z + bias[col0 + 2], 0.0f);
        o.s.w = fmaxf(o.s.w + bias[col0 + 3], 0.0f);
        *(float4*)&C[(size_t)(row0 + r) * BN + col0] = o.f;
    }
}

// ---------------- value head: out[i] = dot(h2[i], Wv) + bv ----------------
__global__ void value_k(const float* __restrict__ Wv, const float* __restrict__ bv,
                        float* __restrict__ out, int n)
{
    int i = blockIdx.x * (blockDim.x >> 5) + (threadIdx.x >> 5);
    int lane = threadIdx.x & 31;
    if (i >= n) return;
    const float* h = g_h2 + (size_t)i * HID;
    float s = 0.0f;
    #pragma unroll
    for (int q = 0; q < 4; q++) {
        int j = lane + 32 * q;
        s = fmaf(h[j], Wv[j], s);
    }
    #pragma unroll
    for (int off = 16; off > 0; off >>= 1)
        s += __shfl_xor_sync(0xFFFFFFFFu, s, off);
    if (lane == 0) out[i] = s + bv[0];
}

// ---------------- launch ----------------
extern "C" void kernel_launch(void* const* d_in, const int* in_sizes, int n_in,
                              void* d_out, int out_size)
{
    const float* feat     = (const float*)d_in[0];
    const void*  ei       = d_in[1];
    const float* W_gcn    = (const float*)d_in[2];
    const float* b_gcn    = (const float*)d_in[3];
    const float* W_sage_l = (const float*)d_in[4];
    const float* b_sage_l = (const float*)d_in[5];
    const float* W_sage_r = (const float*)d_in[6];
    const float* W1       = (const float*)d_in[7];
    const float* b1       = (const float*)d_in[8];
    const float* W2       = (const float*)d_in[9];
    const float* b2       = (const float*)d_in[10];
    const float* W3       = (const float*)d_in[11];
    const float* b3       = (const float*)d_in[12];
    const float* Wv       = (const float*)d_in[13];
    const float* bv       = (const float*)d_in[14];

    const int N = in_sizes[0] / HID;   // 20000
    const int E = in_sizes[1] / 2;     // 640000

    float* means_out  = (float*)d_out;            // [N, 64]
    float* values_out = (float*)d_out + (size_t)N * 64;

    float *p_x, *p_h1, *p_ns, *p_h2;
    cudaGetSymbolAddress((void**)&p_x,  g_x);
    cudaGetSymbolAddress((void**)&p_h1, g_h1);
    cudaGetSymbolAddress((void**)&p_ns, g_ns);
    cudaGetSymbolAddress((void**)&p_h2, g_h2);

    const int TB = 256;
    const int e_blocks  = (E + TB - 1) / TB;
    const int nw_blocks = (N * 32 + TB - 1) / TB;   // warp per node
    const int scan_blocks = (N + 1023) / 1024;      // 20
    const int gemm_blocks = (N + 31) / 32;

    // 1) CSR build
    detect_dtype_k<<<1, 64>>>((const int*)ei);
    zero_cnt_k<<<(N + TB - 1) / TB, TB>>>(N);
    convert_count_k<<<e_blocks, TB>>>(ei, E);
    scanA_k<<<scan_blocks, 1024>>>(N);
    scanB_k<<<1, 64>>>(scan_blocks, N);
    scanC_k<<<scan_blocks, 1024>>>(N);
    fill_k<<<e_blocks, TB>>>(E);

    // 2) GCN: x = feat @ W_gcn ; gather(+selfloop+bias+relu)
    gemm_k<128, 0><<<gemm_blocks, TB>>>(feat, W_gcn, nullptr, p_x, N);
    gcn_gather_k<<<nw_blocks, TB>>>(b_gcn, N);

    // 3) SAGE: neighbor mean ; h2 = relu(mean@Wl + h@Wr + bl)  (fused)
    sage_gather_k<<<nw_blocks, TB>>>(N);
    gemm2_k<<<gemm_blocks, TB>>>(p_ns, W_sage_l, p_h1, W_sage_r, b_sage_l, p_h2, N);

    // 4) policy MLP
    gemm_k<128, 2><<<gemm_blocks, TB>>>(p_h2, W1, b1, p_x, N);
    gemm_k<128, 2><<<gemm_blocks, TB>>>(p_x, W2, b2, p_ns, N);
    gemm_k<64, 0><<<gemm_blocks, TB>>>(p_ns, W3, b3, means_out, N);

    // 5) value head
    value_k<<<(N + 7) / 8, TB>>>(Wv, bv, values_out, N);
}